// round 12
// baseline (speedup 1.0000x reference)
#include <cuda_runtime.h>
#include <cstdint>

#define DINL __device__ __forceinline__

// ---------------- problem constants ----------------
static constexpr int L   = 128;
static constexpr int D   = 768;
static constexpr int KC  = 32;
static constexpr int NCH = D / KC;   // 24
static constexpr int NTHR = 128;

// split point: first NFULL pairs -> kernel A (1 CTA/pair, exactly 3 waves of 296),
// remaining pairs -> kernel B (2 CTAs/pair, 1 wave)
static constexpr int NFULL = 888;

// ---- kernel A layout (R7): 3 stages, full 128x128 tiles ----
static constexpr int RS = 36;
static constexpr int A_TILE_FLOATS  = L * RS;            // 4608
static constexpr int A_STAGE_FLOATS = 2 * A_TILE_FLOATS; // 9216
static constexpr int A_STAGES = 3;
static constexpr int A_HDR = 288;
static constexpr uint32_t A_TILE_BYTES  = A_TILE_FLOATS * 4;
static constexpr uint32_t A_STAGE_BYTES = A_STAGE_FLOATS * 4;
static constexpr uint32_t A_ROWBLK = 16 * RS * 4;
static constexpr uint32_t A_MBAR_OFF = 264 * 4;
static constexpr uint32_t SMEM_A = (A_HDR + A_STAGES * A_STAGE_FLOATS) * 4;  // 111744

// ---- kernel B layout (R8): 4 stages, 64-row A half + full B ----
static constexpr int MH = 64;
static constexpr int B_TILEA_FLOATS = MH * RS;            // 2304
static constexpr int B_TILEB_FLOATS = L * RS;             // 4608
static constexpr int B_STAGE_FLOATS = B_TILEA_FLOATS + B_TILEB_FLOATS;  // 6912
static constexpr int B_STAGES = 4;
static constexpr int B_HDR = 160;
static constexpr uint32_t B_TILEA_BYTES = B_TILEA_FLOATS * 4;
static constexpr uint32_t B_STAGE_BYTES = B_STAGE_FLOATS * 4;
static constexpr uint32_t B_ROWBLK = 16 * RS * 4;
static constexpr uint32_t B_MBAR_OFF = 136 * 4;
static constexpr uint32_t SMEM_B = (B_HDR + B_STAGES * B_STAGE_FLOATS) * 4;  // 111232

// ---------------- PTX helpers ----------------
DINL uint32_t smem_u32(const void* p) {
    uint32_t a;
    asm("{ .reg .u64 t; cvta.to.shared.u64 t, %1; cvt.u32.u64 %0, t; }" : "=r"(a) : "l"(p));
    return a;
}
DINL void cp_async16(uint32_t dst, const void* src) {
    asm volatile("cp.async.cg.shared.global [%0], [%1], 16;" :: "r"(dst), "l"(src) : "memory");
}
DINL void mbar_init(uint32_t a, uint32_t cnt) {
    asm volatile("mbarrier.init.shared.b64 [%0], %1;" :: "r"(a), "r"(cnt) : "memory");
}
DINL void mbar_arrive(uint32_t a) {
    asm volatile("mbarrier.arrive.shared.b64 _, [%0];" :: "r"(a) : "memory");
}
DINL void cp_async_mbar_arrive(uint32_t a) {
    asm volatile("cp.async.mbarrier.arrive.noinc.shared.b64 [%0];" :: "r"(a) : "memory");
}
DINL void mbar_wait(uint32_t a, uint32_t parity) {
    asm volatile(
        "{\n\t.reg .pred P;\n"
        "WL%=:\n\t"
        "mbarrier.try_wait.parity.shared.b64 P, [%0], %1;\n\t"
        "@P bra WD%=;\n\t"
        "bra WL%=;\n"
        "WD%=:\n\t}"
        :: "r"(a), "r"(parity) : "memory");
}
DINL void mma_tf32(float* d, const uint32_t* a, const uint32_t* b) {
    asm volatile(
        "mma.sync.aligned.m16n8k8.row.col.f32.tf32.tf32.f32 "
        "{%0,%1,%2,%3}, {%4,%5,%6,%7}, {%8,%9}, {%0,%1,%2,%3};\n"
        : "+f"(d[0]), "+f"(d[1]), "+f"(d[2]), "+f"(d[3])
        : "r"(a[0]), "r"(a[1]), "r"(a[2]), "r"(a[3]), "r"(b[0]), "r"(b[1]));
}
DINL uint32_t f2u(float x) { return __float_as_uint(x); }

template <int NMT>
DINL void load_a_t(uint32_t (&a)[NMT][4], const float* __restrict__ pA, int k0) {
#pragma unroll
    for (int mt = 0; mt < NMT; mt++) {
        const int base = mt * 16 * RS;
        a[mt][0] = f2u(pA[base + k0]);
        a[mt][1] = f2u(pA[base + 8 * RS + k0]);
        a[mt][2] = f2u(pA[base + k0 + 4]);
        a[mt][3] = f2u(pA[base + 8 * RS + k0 + 4]);
    }
}
DINL void load_b8(uint32_t (&b)[8][2], const float* __restrict__ pB, int k0) {
#pragma unroll
    for (int nt = 0; nt < 8; nt++) {
        b[nt][0] = f2u(pB[nt * 8 * RS + k0]);
        b[nt][1] = f2u(pB[nt * 8 * RS + k0 + 4]);
    }
}

// ============================================================================
// Kernel A (R7): one CTA per pair, pairs 0..NFULL-1. Also zeroes the tail
// outputs (stream order guarantees this completes before kernel B runs).
// ============================================================================
__global__ void __launch_bounds__(NTHR, 2)
som_full(const float* __restrict__ in, float* __restrict__ out, int npairs) {
    extern __shared__ float smem[];
    float* rowbuf = smem;
    float* wsum   = smem + 256;
    float* tiles  = smem + A_HDR;

    const int tid  = threadIdx.x;
    const int wid  = tid >> 5;
    const int lane = tid & 31;
    const int wr   = wid >> 1;
    const int wc   = wid & 1;
    const int qid  = lane >> 2;
    const int qlan = lane & 3;

    // zero the atomic targets for kernel B (pairs NFULL..npairs-1)
    if (tid == 0 && blockIdx.x < (unsigned)(npairs - NFULL))
        out[NFULL + blockIdx.x] = 0.0f;

    const uint32_t smem_b = smem_u32(smem);
    const uint32_t mb_full = smem_b + A_MBAR_OFF;
    const uint32_t mb_free = smem_b + A_MBAR_OFF + 24;

    if (tid == 0) {
#pragma unroll
        for (int s = 0; s < A_STAGES; s++) {
            mbar_init(mb_full + 8u * s, NTHR);
            mbar_init(mb_free + 8u * s, NTHR);
        }
    }
    __syncthreads();

    const size_t pair = blockIdx.x;
    const float* ctx = in + pair * (size_t)(2 * L * D);

    const int lrow = tid >> 3;
    const int lseg = tid & 7;
    const float* gbase = ctx + (size_t)lrow * D + lseg * 4;
    const uint32_t dst0 = smem_u32(tiles) + (uint32_t)(lrow * RS + lseg * 4) * 4u;

    const int idxA = (wr * 64 + qid) * RS + qlan;
    const int idxB = (wc * 64 + qid) * RS + qlan;

    float acc[4][8][4];
#pragma unroll
    for (int mt = 0; mt < 4; mt++)
#pragma unroll
        for (int nt = 0; nt < 8; nt++)
#pragma unroll
            for (int r = 0; r < 4; r++) acc[mt][nt][r] = 0.0f;

    auto issue = [&](int c) {
        const float* pa = gbase + c * KC;
        const uint32_t da = dst0 + (uint32_t)(c % A_STAGES) * A_STAGE_BYTES;
#pragma unroll
        for (int i = 0; i < 8; i++) {
            cp_async16(da + i * A_ROWBLK, pa + (size_t)i * 16 * D);
            cp_async16(da + A_TILE_BYTES + i * A_ROWBLK,
                       pa + (size_t)L * D + (size_t)i * 16 * D);
        }
        cp_async_mbar_arrive(mb_full + 8u * (uint32_t)(c % A_STAGES));
    };

    issue(0);
    issue(1);

    uint32_t A[2][4][4];
    uint32_t Bf[2][8][2];

#pragma unroll 1
    for (int c = 0; c < NCH; c++) {
        const uint32_t s = (uint32_t)(c % A_STAGES);
        mbar_wait(mb_full + 8u * s, (uint32_t)((c / 3) & 1));

        const float* sA = tiles + (size_t)s * A_STAGE_FLOATS;
        const float* pA = sA + idxA;
        const float* pB = sA + A_TILE_FLOATS + idxB;

        load_a_t<4>(A[0], pA, 0);
        load_b8(Bf[0], pB, 0);
        load_a_t<4>(A[1], pA, 8);
        load_b8(Bf[1], pB, 8);

#pragma unroll
        for (int mt = 0; mt < 4; mt++)
#pragma unroll
            for (int nt = 0; nt < 8; nt++)
                mma_tf32(acc[mt][nt], A[0][mt], Bf[0][nt]);

        if (c + 2 < NCH) {
            if (c >= 1)
                mbar_wait(mb_free + 8u * (uint32_t)((c + 2) % A_STAGES),
                          (uint32_t)(((c - 1) / 3) & 1));
            issue(c + 2);
        }

#pragma unroll
        for (int ks = 1; ks < 4; ks++) {
            const int cur = ks & 1, nxt = cur ^ 1;
            if (ks < 3) {
                load_a_t<4>(A[nxt], pA, (ks + 1) * 8);
                load_b8(Bf[nxt], pB, (ks + 1) * 8);
            }
#pragma unroll
            for (int mt = 0; mt < 4; mt++)
#pragma unroll
                for (int nt = 0; nt < 8; nt++)
                    mma_tf32(acc[mt][nt], A[cur][mt], Bf[cur][nt]);
        }

        mbar_arrive(mb_free + 8u * s);
    }

#pragma unroll
    for (int mt = 0; mt < 4; mt++) {
#pragma unroll
        for (int h = 0; h < 2; h++) {
            float m = __int_as_float(0xff800000);
#pragma unroll
            for (int nt = 0; nt < 8; nt++) {
                m = fmaxf(m, acc[mt][nt][2 * h]);
                m = fmaxf(m, acc[mt][nt][2 * h + 1]);
            }
            m = fmaxf(m, __shfl_xor_sync(0xffffffffu, m, 1));
            m = fmaxf(m, __shfl_xor_sync(0xffffffffu, m, 2));
            if (qlan == 0)
                rowbuf[wc * 128 + wr * 64 + mt * 16 + h * 8 + qid] = m;
        }
    }
    __syncthreads();

    {
        float v = fmaxf(rowbuf[tid], rowbuf[128 + tid]);
#pragma unroll
        for (int o = 16; o > 0; o >>= 1) v += __shfl_xor_sync(0xffffffffu, v, o);
        if (lane == 0) wsum[wid] = v;
    }
    __syncthreads();
    if (tid == 0) out[pair] = wsum[0] + wsum[1] + wsum[2] + wsum[3];
}

// ============================================================================
// Kernel B (R8): two CTAs per pair (64 ctx rows each), pairs NFULL.. .
// Partial sums combined via atomicAdd (targets zeroed by kernel A).
// ============================================================================
__global__ void __launch_bounds__(NTHR, 2)
som_half(const float* __restrict__ in, float* __restrict__ out) {
    extern __shared__ float smem[];
    float* rowbuf = smem;            // [2][64]
    float* wsum   = smem + 128;      // [4]
    float* tiles  = smem + B_HDR;

    const int tid  = threadIdx.x;
    const int wid  = tid >> 5;
    const int lane = tid & 31;
    const int wr   = wid >> 1;
    const int wc   = wid & 1;
    const int qid  = lane >> 2;
    const int qlan = lane & 3;

    const uint32_t smem_b = smem_u32(smem);
    const uint32_t mb_full = smem_b + B_MBAR_OFF;
    const uint32_t mb_free = smem_b + B_MBAR_OFF + 32;

    if (tid == 0) {
#pragma unroll
        for (int s = 0; s < B_STAGES; s++) {
            mbar_init(mb_full + 8u * s, NTHR);
            mbar_init(mb_free + 8u * s, NTHR);
        }
    }
    __syncthreads();

    const size_t pair = NFULL + (blockIdx.x >> 1);
    const int    half = blockIdx.x & 1;
    const float* ctx = in + pair * (size_t)(2 * L * D);
    const float* ent = ctx + (size_t)L * D;

    const int lrow = tid >> 3;
    const int lseg = tid & 7;
    const float* gbaseA = ctx + (size_t)(half * MH + lrow) * D + lseg * 4;
    const float* gbaseB = ent + (size_t)lrow * D + lseg * 4;
    const uint32_t dst0 = smem_u32(tiles) + (uint32_t)(lrow * RS + lseg * 4) * 4u;

    const int idxA = (wr * 32 + qid) * RS + qlan;
    const int idxB = (wc * 64 + qid) * RS + qlan;

    float acc[2][8][4];
#pragma unroll
    for (int mt = 0; mt < 2; mt++)
#pragma unroll
        for (int nt = 0; nt < 8; nt++)
#pragma unroll
            for (int r = 0; r < 4; r++) acc[mt][nt][r] = 0.0f;

    auto issue = [&](int c) {
        const int coff = c * KC;
        const uint32_t da = dst0 + (uint32_t)(c % B_STAGES) * B_STAGE_BYTES;
#pragma unroll
        for (int i = 0; i < 4; i++)
            cp_async16(da + i * B_ROWBLK, gbaseA + (size_t)i * 16 * D + coff);
#pragma unroll
        for (int i = 0; i < 8; i++)
            cp_async16(da + B_TILEA_BYTES + i * B_ROWBLK,
                       gbaseB + (size_t)i * 16 * D + coff);
        cp_async_mbar_arrive(mb_full + 8u * (uint32_t)(c % B_STAGES));
    };

    issue(0);
    issue(1);
    issue(2);

    uint32_t A[2][2][4];
    uint32_t Bf[2][8][2];

#pragma unroll 1
    for (int c = 0; c < NCH; c++) {
        const uint32_t s = (uint32_t)(c % B_STAGES);
        mbar_wait(mb_full + 8u * s, (uint32_t)((c / B_STAGES) & 1));

        const float* sA = tiles + (size_t)s * B_STAGE_FLOATS;
        const float* pA = sA + idxA;
        const float* pB = sA + B_TILEA_FLOATS + idxB;

        load_a_t<2>(A[0], pA, 0);
        load_b8(Bf[0], pB, 0);
        load_a_t<2>(A[1], pA, 8);
        load_b8(Bf[1], pB, 8);

#pragma unroll
        for (int mt = 0; mt < 2; mt++)
#pragma unroll
            for (int nt = 0; nt < 8; nt++)
                mma_tf32(acc[mt][nt], A[0][mt], Bf[0][nt]);

        if (c + 3 < NCH) {
            if (c >= 1)
                mbar_wait(mb_free + 8u * (uint32_t)((c - 1) % B_STAGES),
                          (uint32_t)(((c - 1) / B_STAGES) & 1));
            issue(c + 3);
        }

#pragma unroll
        for (int ks = 1; ks < 4; ks++) {
            const int cur = ks & 1, nxt = cur ^ 1;
            if (ks < 3) {
                load_a_t<2>(A[nxt], pA, (ks + 1) * 8);
                load_b8(Bf[nxt], pB, (ks + 1) * 8);
            }
#pragma unroll
            for (int mt = 0; mt < 2; mt++)
#pragma unroll
                for (int nt = 0; nt < 8; nt++)
                    mma_tf32(acc[mt][nt], A[cur][mt], Bf[cur][nt]);
        }

        mbar_arrive(mb_free + 8u * s);
    }

#pragma unroll
    for (int mt = 0; mt < 2; mt++) {
#pragma unroll
        for (int h = 0; h < 2; h++) {
            float m = __int_as_float(0xff800000);
#pragma unroll
            for (int nt = 0; nt < 8; nt++) {
                m = fmaxf(m, acc[mt][nt][2 * h]);
                m = fmaxf(m, acc[mt][nt][2 * h + 1]);
            }
            m = fmaxf(m, __shfl_xor_sync(0xffffffffu, m, 1));
            m = fmaxf(m, __shfl_xor_sync(0xffffffffu, m, 2));
            if (qlan == 0)
                rowbuf[wc * 64 + wr * 32 + mt * 16 + h * 8 + qid] = m;
        }
    }
    __syncthreads();

    if (tid < 64) {
        float v = fmaxf(rowbuf[tid], rowbuf[64 + tid]);
#pragma unroll
        for (int o = 16; o > 0; o >>= 1) v += __shfl_xor_sync(0xffffffffu, v, o);
        if (lane == 0) wsum[wid] = v;
    }
    __syncthreads();
    if (tid == 0) atomicAdd(&out[pair], wsum[0] + wsum[1]);
}

// ---------------- launch ----------------
extern "C" void kernel_launch(void* const* d_in, const int* in_sizes, int n_in,
                              void* d_out, int out_size) {
    const float* in = (const float*)d_in[0];
    float* out = (float*)d_out;
    const int pairs = in_sizes[0] / (2 * L * D);  // 1024

    cudaFuncSetAttribute(som_full, cudaFuncAttributeMaxDynamicSharedMemorySize, SMEM_A);
    cudaFuncSetAttribute(som_half, cudaFuncAttributeMaxDynamicSharedMemorySize, SMEM_B);

    // phase A: first NFULL pairs, 1 CTA each (exactly 3 waves of 296);
    // also zeroes the tail outputs used by phase B's atomics.
    som_full<<<NFULL, NTHR, SMEM_A>>>(in, out, pairs);
    // phase B: remaining pairs, 2 CTAs each (1 wave)
    const int tail = pairs - NFULL;
    if (tail > 0)
        som_half<<<2 * tail, NTHR, SMEM_B>>>(in, out);
}

// round 13
// speedup vs baseline: 1.0043x; 1.0043x over previous
#include <cuda_runtime.h>
#include <cstdint>

#define DINL __device__ __forceinline__

// ---------------- problem constants ----------------
static constexpr int L   = 128;  // rows per operand tile (M and N)
static constexpr int D   = 768;  // reduction dim
static constexpr int KC  = 32;   // fp32 elements per K-chunk
static constexpr int NCH = D / KC;  // 24 chunks
static constexpr int STAGES = 3;
static constexpr int NTHR = 128; // 4 warps, 2x2 grid of 64x64 warp tiles

// smem: padded row stride of 36 floats -> conflict-free LDS and STS patterns
static constexpr int RS = 36;                         // row stride in floats
static constexpr int TILE_FLOATS  = L * RS;           // 4608 floats = 18 KB
static constexpr int STAGE_FLOATS = 2 * TILE_FLOATS;  // A + B = 36 KB
static constexpr int HDR_FLOATS   = 288;              // rowbuf[256]+wsum[4]+mbars
static constexpr uint32_t TILE_BYTES  = TILE_FLOATS * 4;   // 18432
static constexpr uint32_t STAGE_BYTES = STAGE_FLOATS * 4;  // 36864
static constexpr uint32_t ROWBLK_BYTES = 16 * RS * 4;      // 2304 (16-row block)
static constexpr uint32_t MBAR_OFF = 264 * 4;              // byte offset of mbarriers
static constexpr uint32_t SMEM_DYN =
    (HDR_FLOATS + STAGES * STAGE_FLOATS) * sizeof(float);  // 111,744 B

// ---------------- PTX helpers ----------------
DINL uint32_t smem_u32(const void* p) {
    uint32_t a;
    asm("{ .reg .u64 t; cvta.to.shared.u64 t, %1; cvt.u32.u64 %0, t; }" : "=r"(a) : "l"(p));
    return a;
}
DINL void cp_async16(uint32_t dst, const void* src) {
    asm volatile("cp.async.cg.shared.global [%0], [%1], 16;" :: "r"(dst), "l"(src) : "memory");
}
DINL void mbar_init(uint32_t a, uint32_t cnt) {
    asm volatile("mbarrier.init.shared.b64 [%0], %1;" :: "r"(a), "r"(cnt) : "memory");
}
DINL void mbar_arrive(uint32_t a) {
    asm volatile("mbarrier.arrive.shared.b64 _, [%0];" :: "r"(a) : "memory");
}
// arrive on mbar when all of this thread's prior cp.async have completed
DINL void cp_async_mbar_arrive(uint32_t a) {
    asm volatile("cp.async.mbarrier.arrive.noinc.shared.b64 [%0];" :: "r"(a) : "memory");
}
DINL void mbar_wait(uint32_t a, uint32_t parity) {
    asm volatile(
        "{\n\t.reg .pred P;\n"
        "WL%=:\n\t"
        "mbarrier.try_wait.parity.shared.b64 P, [%0], %1;\n\t"
        "@P bra WD%=;\n\t"
        "bra WL%=;\n"
        "WD%=:\n\t}"
        :: "r"(a), "r"(parity) : "memory");
}

DINL void mma_tf32(float* d, const uint32_t* a, const uint32_t* b) {
    asm volatile(
        "mma.sync.aligned.m16n8k8.row.col.f32.tf32.tf32.f32 "
        "{%0,%1,%2,%3}, {%4,%5,%6,%7}, {%8,%9}, {%0,%1,%2,%3};\n"
        : "+f"(d[0]), "+f"(d[1]), "+f"(d[2]), "+f"(d[3])
        : "r"(a[0]), "r"(a[1]), "r"(a[2]), "r"(a[3]), "r"(b[0]), "r"(b[1]));
}

DINL uint32_t f2u(float x) { return __float_as_uint(x); }

// A fragments: four 16-row m-tiles at k-offset k0. pA = sA + (wr*64+qid)*RS + qlan.
DINL void load_a(uint32_t (&a)[4][4], const float* __restrict__ pA, int k0) {
#pragma unroll
    for (int mt = 0; mt < 4; mt++) {
        const int base = mt * 16 * RS;
        a[mt][0] = f2u(pA[base + k0]);
        a[mt][1] = f2u(pA[base + 8 * RS + k0]);
        a[mt][2] = f2u(pA[base + k0 + 4]);
        a[mt][3] = f2u(pA[base + 8 * RS + k0 + 4]);
    }
}
// B fragments: eight 8-col n-tiles at k-offset k0. pB = sB + (wc*64+qid)*RS + qlan.
DINL void load_b(uint32_t (&b)[8][2], const float* __restrict__ pB, int k0) {
#pragma unroll
    for (int nt = 0; nt < 8; nt++) {
        b[nt][0] = f2u(pB[nt * 8 * RS + k0]);
        b[nt][1] = f2u(pB[nt * 8 * RS + k0 + 4]);
    }
}

// ---------------- kernel ----------------
// One CTA (128 threads) per (b,k) pair. sim = ctx @ ent^T via tf32 mma.sync;
// out[pair] = sum over rows of rowwise max of sim.
// R7 structure + cross-chunk fragment preloading: next chunk's ks=0 fragments
// are loaded at the current chunk's tail (after full[c+1] acquire-wait),
// overlapped with ks=3's MMAs, so the MMA pipe never idles at chunk start.
__global__ void __launch_bounds__(NTHR, 2)
som_kernel(const float* __restrict__ in, float* __restrict__ out) {
    extern __shared__ float smem[];
    float* rowbuf = smem;            // [2][128] rowwise maxima (per col-half)
    float* wsum   = smem + 256;      // [4]
    float* tiles  = smem + HDR_FLOATS;

    const int tid  = threadIdx.x;
    const int wid  = tid >> 5;
    const int lane = tid & 31;
    const int wr   = wid >> 1;  // warp row  (rows wr*64 .. +63)
    const int wc   = wid & 1;   // warp col  (cols wc*64 .. +63)
    const int qid  = lane >> 2; // 0..7
    const int qlan = lane & 3;  // 0..3

    const uint32_t smem_b = smem_u32(smem);
    const uint32_t mb_full = smem_b + MBAR_OFF;       // full[0..2]
    const uint32_t mb_free = smem_b + MBAR_OFF + 24;  // free[0..2]

    if (tid == 0) {
#pragma unroll
        for (int s = 0; s < STAGES; s++) {
            mbar_init(mb_full + 8u * s, NTHR);
            mbar_init(mb_free + 8u * s, NTHR);
        }
    }
    __syncthreads();

    const size_t pair = blockIdx.x;
    const float* ctx = in + pair * (size_t)(2 * L * D);

    // ---- cp.async plan: 16x 16B per thread per chunk (8 A-rows + 8 B-rows) ----
    const int lrow = tid >> 3;  // 0..15
    const int lseg = tid & 7;   // 0..7
    const float* gbase = ctx + (size_t)lrow * D + lseg * 4;
    const uint32_t dst0 = smem_u32(tiles) + (uint32_t)(lrow * RS + lseg * 4) * 4u;

    // frag LDS base indices
    const int idxA = (wr * 64 + qid) * RS + qlan;
    const int idxB = (wc * 64 + qid) * RS + qlan;

    // ---- accumulators: 4 m-tiles x 8 n-tiles x 4 regs ----
    float acc[4][8][4];
#pragma unroll
    for (int mt = 0; mt < 4; mt++)
#pragma unroll
        for (int nt = 0; nt < 8; nt++)
#pragma unroll
            for (int r = 0; r < 4; r++) acc[mt][nt][r] = 0.0f;

    // issue cp.async for chunk c into stage c%3, then arm full[s]
    auto issue = [&](int c) {
        const float* pa = gbase + c * KC;
        const uint32_t da = dst0 + (uint32_t)(c % STAGES) * STAGE_BYTES;
#pragma unroll
        for (int i = 0; i < 8; i++) {
            cp_async16(da + i * ROWBLK_BYTES, pa + (size_t)i * 16 * D);
            cp_async16(da + TILE_BYTES + i * ROWBLK_BYTES,
                       pa + (size_t)L * D + (size_t)i * 16 * D);
        }
        cp_async_mbar_arrive(mb_full + 8u * (uint32_t)(c % STAGES));
    };

    // prologue: chunks 0 and 1 in flight; preload chunk 0's ks=0 fragments
    issue(0);
    issue(1);

    uint32_t A[2][4][4];
    uint32_t Bf[2][8][2];

    mbar_wait(mb_full + 0u, 0u);  // chunk 0 visible (acquire)
    {
        const float* sA0 = tiles;
        load_a(A[0], sA0 + idxA, 0);
        load_b(Bf[0], sA0 + TILE_FLOATS + idxB, 0);
    }

#pragma unroll 1
    for (int c = 0; c < NCH; c++) {
        const uint32_t s = (uint32_t)(c % STAGES);
        const float* sA = tiles + (size_t)s * STAGE_FLOATS;
        const float* pA = sA + idxA;
        const float* pB = sA + TILE_FLOATS + idxB;

        // ks=0 fragments already in A[0]/Bf[0] (loaded at prior chunk's tail)
        load_a(A[1], pA, 8);
        load_b(Bf[1], pB, 8);

        // ks = 0 MMAs
#pragma unroll
        for (int mt = 0; mt < 4; mt++)
#pragma unroll
            for (int nt = 0; nt < 8; nt++)
                mma_tf32(acc[mt][nt], A[0][mt], Bf[0][nt]);

        // mid-compute pipeline refill (unchanged from R7)
        if (c + 2 < NCH) {
            if (c >= 1)
                mbar_wait(mb_free + 8u * (uint32_t)((c + 2) % STAGES),
                          (uint32_t)(((c - 1) / 3) & 1));
            issue(c + 2);
        }

        // load ks=2, MMA ks=1
        load_a(A[0], pA, 16);
        load_b(Bf[0], pB, 16);
#pragma unroll
        for (int mt = 0; mt < 4; mt++)
#pragma unroll
            for (int nt = 0; nt < 8; nt++)
                mma_tf32(acc[mt][nt], A[1][mt], Bf[1][nt]);

        // load ks=3 (LAST reads of stage s), MMA ks=2, release stage
        load_a(A[1], pA, 24);
        load_b(Bf[1], pB, 24);
#pragma unroll
        for (int mt = 0; mt < 4; mt++)
#pragma unroll
            for (int nt = 0; nt < 8; nt++)
                mma_tf32(acc[mt][nt], A[0][mt], Bf[0][nt]);
        mbar_arrive(mb_free + 8u * s);  // orders the ks=3 LDS reads above

        // boundary hiding: acquire next chunk, preload its ks=0 fragments,
        // then run ks=3 MMAs underneath the LDS latency.
        if (c + 1 < NCH) {
            const uint32_t s2 = (uint32_t)((c + 1) % STAGES);
            mbar_wait(mb_full + 8u * s2, (uint32_t)(((c + 1) / 3) & 1));
            const float* sA2 = tiles + (size_t)s2 * STAGE_FLOATS;
            load_a(A[0], sA2 + idxA, 0);
            load_b(Bf[0], sA2 + TILE_FLOATS + idxB, 0);
        }

        // ks = 3 MMAs
#pragma unroll
        for (int mt = 0; mt < 4; mt++)
#pragma unroll
            for (int nt = 0; nt < 8; nt++)
                mma_tf32(acc[mt][nt], A[1][mt], Bf[1][nt]);
    }

    // ---- epilogue: rowwise max over this warp's 64 cols, then combine ----
    // acc reg r holds (row = wr*64 + mt*16 + 8*(r>>1) + qid, col = 2*qlan + (r&1) + nt*8)
#pragma unroll
    for (int mt = 0; mt < 4; mt++) {
#pragma unroll
        for (int h = 0; h < 2; h++) {
            float m = __int_as_float(0xff800000);
#pragma unroll
            for (int nt = 0; nt < 8; nt++) {
                m = fmaxf(m, acc[mt][nt][2 * h]);
                m = fmaxf(m, acc[mt][nt][2 * h + 1]);
            }
            m = fmaxf(m, __shfl_xor_sync(0xffffffffu, m, 1));
            m = fmaxf(m, __shfl_xor_sync(0xffffffffu, m, 2));
            if (qlan == 0)
                rowbuf[wc * 128 + wr * 64 + mt * 16 + h * 8 + qid] = m;
        }
    }
    __syncthreads();

    {
        float v = fmaxf(rowbuf[tid], rowbuf[128 + tid]);
#pragma unroll
        for (int o = 16; o > 0; o >>= 1) v += __shfl_xor_sync(0xffffffffu, v, o);
        if (lane == 0) wsum[wid] = v;
    }
    __syncthreads();
    if (tid == 0) out[pair] = wsum[0] + wsum[1] + wsum[2] + wsum[3];
}

// ---------------- launch ----------------
extern "C" void kernel_launch(void* const* d_in, const int* in_sizes, int n_in,
                              void* d_out, int out_size) {
    const float* in = (const float*)d_in[0];
    float* out = (float*)d_out;
    const int pairs = in_sizes[0] / (2 * L * D);  // B*K = 1024

    cudaFuncSetAttribute(som_kernel, cudaFuncAttributeMaxDynamicSharedMemorySize, SMEM_DYN);
    som_kernel<<<pairs, NTHR, SMEM_DYN>>>(in, out);
}

// round 14
// speedup vs baseline: 1.0257x; 1.0213x over previous
#include <cuda_runtime.h>
#include <cstdint>

#define DINL __device__ __forceinline__

// ---------------- problem constants ----------------
static constexpr int L   = 128;  // rows per operand tile (M and N)
static constexpr int D   = 768;  // reduction dim
static constexpr int KC  = 32;   // fp32 elements per K-chunk
static constexpr int NCH = D / KC;  // 24 chunks
static constexpr int STAGES = 3;
static constexpr int NTHR = 128; // 4 warps, 2x2 grid of 64x64 warp tiles

// smem: padded row stride of 36 floats -> conflict-free LDS and STS patterns
static constexpr int RS = 36;                         // row stride in floats
static constexpr int TILE_FLOATS  = L * RS;           // 4608 floats = 18 KB
static constexpr int STAGE_FLOATS = 2 * TILE_FLOATS;  // A + B = 36 KB
static constexpr int HDR_FLOATS   = 288;              // rowbuf[256]+wsum[4]+pair+mbars
static constexpr uint32_t TILE_BYTES  = TILE_FLOATS * 4;   // 18432
static constexpr uint32_t STAGE_BYTES = STAGE_FLOATS * 4;  // 36864
static constexpr uint32_t ROWBLK_BYTES = 16 * RS * 4;      // 2304 (16-row block)
static constexpr uint32_t MBAR_OFF = 264 * 4;              // byte offset of mbarriers
static constexpr uint32_t SMEM_DYN =
    (HDR_FLOATS + STAGES * STAGE_FLOATS) * sizeof(float);  // 111,744 B

// work-stealing pair counter (reset by init kernel each launch)
__device__ int g_pair_counter;

// ---------------- PTX helpers ----------------
DINL uint32_t smem_u32(const void* p) {
    uint32_t a;
    asm("{ .reg .u64 t; cvta.to.shared.u64 t, %1; cvt.u32.u64 %0, t; }" : "=r"(a) : "l"(p));
    return a;
}
DINL void cp_async16(uint32_t dst, const void* src) {
    asm volatile("cp.async.cg.shared.global [%0], [%1], 16;" :: "r"(dst), "l"(src) : "memory");
}
DINL void mbar_init(uint32_t a, uint32_t cnt) {
    asm volatile("mbarrier.init.shared.b64 [%0], %1;" :: "r"(a), "r"(cnt) : "memory");
}
DINL void mbar_arrive(uint32_t a) {
    asm volatile("mbarrier.arrive.shared.b64 _, [%0];" :: "r"(a) : "memory");
}
// arrive on mbar when all of this thread's prior cp.async have completed
DINL void cp_async_mbar_arrive(uint32_t a) {
    asm volatile("cp.async.mbarrier.arrive.noinc.shared.b64 [%0];" :: "r"(a) : "memory");
}
DINL void mbar_wait(uint32_t a, uint32_t parity) {
    asm volatile(
        "{\n\t.reg .pred P;\n"
        "WL%=:\n\t"
        "mbarrier.try_wait.parity.shared.b64 P, [%0], %1;\n\t"
        "@P bra WD%=;\n\t"
        "bra WL%=;\n"
        "WD%=:\n\t}"
        :: "r"(a), "r"(parity) : "memory");
}

DINL void mma_tf32(float* d, const uint32_t* a, const uint32_t* b) {
    asm volatile(
        "mma.sync.aligned.m16n8k8.row.col.f32.tf32.tf32.f32 "
        "{%0,%1,%2,%3}, {%4,%5,%6,%7}, {%8,%9}, {%0,%1,%2,%3};\n"
        : "+f"(d[0]), "+f"(d[1]), "+f"(d[2]), "+f"(d[3])
        : "r"(a[0]), "r"(a[1]), "r"(a[2]), "r"(a[3]), "r"(b[0]), "r"(b[1]));
}

DINL uint32_t f2u(float x) { return __float_as_uint(x); }

// A fragments: four 16-row m-tiles at k-offset k0. pA = sA + (wr*64+qid)*RS + qlan.
DINL void load_a(uint32_t (&a)[4][4], const float* __restrict__ pA, int k0) {
#pragma unroll
    for (int mt = 0; mt < 4; mt++) {
        const int base = mt * 16 * RS;
        a[mt][0] = f2u(pA[base + k0]);
        a[mt][1] = f2u(pA[base + 8 * RS + k0]);
        a[mt][2] = f2u(pA[base + k0 + 4]);
        a[mt][3] = f2u(pA[base + 8 * RS + k0 + 4]);
    }
}
// B fragments: eight 8-col n-tiles at k-offset k0. pB = sB + (wc*64+qid)*RS + qlan.
DINL void load_b(uint32_t (&b)[8][2], const float* __restrict__ pB, int k0) {
#pragma unroll
    for (int nt = 0; nt < 8; nt++) {
        b[nt][0] = f2u(pB[nt * 8 * RS + k0]);
        b[nt][1] = f2u(pB[nt * 8 * RS + k0 + 4]);
    }
}

__global__ void reset_counter(int v) { g_pair_counter = v; }

// ---------------- kernel ----------------
// Persistent CTAs (2 per SM), work-stealing over (b,k) pairs. Per pair:
// sim = ctx @ ent^T via tf32 mma.sync (R7 chunk body, unchanged);
// out[pair] = sum over rows of rowwise max of sim.
// The 3-stage cp.async/mbarrier pipeline runs CONTINUOUSLY across pair
// boundaries: global chunk counter G drives stage/parity; chunks 22/23 of
// pair i refill with chunks 0/1 of pair i+1 (index fetched at chunk 20 via
// atomicAdd, published through a 1-count mbarrier).
__global__ void __launch_bounds__(NTHR, 2)
som_kernel(const float* __restrict__ in, float* __restrict__ out, int npairs) {
    extern __shared__ float smem[];
    float* rowbuf = smem;            // [2][128] rowwise maxima (per col-half)
    float* wsum   = smem + 256;      // [4]
    int*   pslot  = (int*)(smem + 260);
    float* tiles  = smem + HDR_FLOATS;

    const int tid  = threadIdx.x;
    const int wid  = tid >> 5;
    const int lane = tid & 31;
    const int wr   = wid >> 1;  // warp row  (rows wr*64 .. +63)
    const int wc   = wid & 1;   // warp col  (cols wc*64 .. +63)
    const int qid  = lane >> 2; // 0..7
    const int qlan = lane & 3;  // 0..3

    const uint32_t smem_b = smem_u32(smem);
    const uint32_t mb_full = smem_b + MBAR_OFF;       // full[0..2]
    const uint32_t mb_free = smem_b + MBAR_OFF + 24;  // free[0..2]
    const uint32_t mb_pair = smem_b + MBAR_OFF + 48;  // next-pair broadcast

    if (tid == 0) {
#pragma unroll
        for (int s = 0; s < STAGES; s++) {
            mbar_init(mb_full + 8u * s, NTHR);
            mbar_init(mb_free + 8u * s, NTHR);
        }
        mbar_init(mb_pair, 1);
    }
    __syncthreads();

    // ---- cp.async plan: 16x 16B per thread per chunk (8 A-rows + 8 B-rows) ----
    const int lrow = tid >> 3;  // 0..15
    const int lseg = tid & 7;   // 0..7
    const uint32_t goff = (uint32_t)(lrow * D + lseg * 4);  // per-thread elem off
    const uint32_t dst0 = smem_u32(tiles) + (uint32_t)(lrow * RS + lseg * 4) * 4u;

    // frag LDS base indices
    const int idxA = (wr * 64 + qid) * RS + qlan;
    const int idxB = (wc * 64 + qid) * RS + qlan;

    int pair = blockIdx.x;  // grid <= npairs guaranteed by launcher
    const float* gbase = in + (size_t)pair * (2 * L * D) + goff;

    // issue cp.async for one chunk (src = gbase + chunk*KC) into stage s
    auto issue = [&](const float* src, uint32_t s) {
        const uint32_t da = dst0 + s * STAGE_BYTES;
#pragma unroll
        for (int i = 0; i < 8; i++) {
            cp_async16(da + i * ROWBLK_BYTES, src + (size_t)i * 16 * D);
            cp_async16(da + TILE_BYTES + i * ROWBLK_BYTES,
                       src + (size_t)L * D + (size_t)i * 16 * D);
        }
        cp_async_mbar_arrive(mb_full + 8u * s);
    };

    // prologue: global chunks 0,1 (pair chunks 0,1) in flight
    issue(gbase, 0u);
    issue(gbase + KC, 1u);

    float acc[4][8][4];
    uint32_t A[2][4][4];
    uint32_t Bf[2][8][2];
    uint32_t G = 0;   // global chunk counter (continuous across pairs)
    int pit = 0;      // pair iteration (parity for mb_pair)

    for (;;) {
#pragma unroll
        for (int mt = 0; mt < 4; mt++)
#pragma unroll
            for (int nt = 0; nt < 8; nt++)
#pragma unroll
                for (int r = 0; r < 4; r++) acc[mt][nt][r] = 0.0f;

        int nxt_pair = 0x7fffffff;
        const float* gnxt = nullptr;

#pragma unroll 1
        for (int c = 0; c < NCH; c++, G++) {
            const uint32_t s = G % 3u;
            mbar_wait(mb_full + 8u * s, (G / 3u) & 1u);  // chunk visible

            const float* sA = tiles + (size_t)s * STAGE_FLOATS;
            const float* pA = sA + idxA;
            const float* pB = sA + TILE_FLOATS + idxB;

            load_a(A[0], pA, 0);
            load_b(Bf[0], pB, 0);
            load_a(A[1], pA, 8);
            load_b(Bf[1], pB, 8);

            // ks = 0 MMAs
#pragma unroll
            for (int mt = 0; mt < 4; mt++)
#pragma unroll
                for (int nt = 0; nt < 8; nt++)
                    mma_tf32(acc[mt][nt], A[0][mt], Bf[0][nt]);

            // steal next pair early so its base is ready for refill at c=22
            if (c == 20 && tid == 0) {
                *pslot = atomicAdd(&g_pair_counter, 1);
                mbar_arrive(mb_pair);
            }

            // mid-compute pipeline refill (R7 position); crosses pair boundary
            {
                const float* src = nullptr;
                if (c + 2 < NCH) {
                    src = gbase + (c + 2) * KC;
                } else {
                    if (c == 22) {
                        mbar_wait(mb_pair, (uint32_t)(pit & 1));
                        nxt_pair = *pslot;
                        gnxt = in + (size_t)nxt_pair * (2 * L * D) + goff;
                    }
                    if (nxt_pair < npairs) src = gnxt + (c + 2 - NCH) * KC;
                }
                if (src) {
                    if (G >= 1)
                        mbar_wait(mb_free + 8u * ((G + 2u) % 3u),
                                  ((G - 1u) / 3u) & 1u);
                    issue(src, (G + 2u) % 3u);
                }
            }

            // ks = 1..3 (R7 body)
#pragma unroll
            for (int ks = 1; ks < 4; ks++) {
                const int cur = ks & 1, nxt = cur ^ 1;
                if (ks < 3) {
                    load_a(A[nxt], pA, (ks + 1) * 8);
                    load_b(Bf[nxt], pB, (ks + 1) * 8);
                }
#pragma unroll
                for (int mt = 0; mt < 4; mt++)
#pragma unroll
                    for (int nt = 0; nt < 8; nt++)
                        mma_tf32(acc[mt][nt], A[cur][mt], Bf[cur][nt]);
            }

            mbar_arrive(mb_free + 8u * s);  // done reading stage s
        }

        // ---- per-pair epilogue: rowwise max over this warp's 64 cols ----
#pragma unroll
        for (int mt = 0; mt < 4; mt++) {
#pragma unroll
            for (int h = 0; h < 2; h++) {
                float m = __int_as_float(0xff800000);
#pragma unroll
                for (int nt = 0; nt < 8; nt++) {
                    m = fmaxf(m, acc[mt][nt][2 * h]);
                    m = fmaxf(m, acc[mt][nt][2 * h + 1]);
                }
                m = fmaxf(m, __shfl_xor_sync(0xffffffffu, m, 1));
                m = fmaxf(m, __shfl_xor_sync(0xffffffffu, m, 2));
                if (qlan == 0)
                    rowbuf[wc * 128 + wr * 64 + mt * 16 + h * 8 + qid] = m;
            }
        }
        __syncthreads();

        {
            float v = fmaxf(rowbuf[tid], rowbuf[128 + tid]);
#pragma unroll
            for (int o = 16; o > 0; o >>= 1) v += __shfl_xor_sync(0xffffffffu, v, o);
            if (lane == 0) wsum[wid] = v;
        }
        __syncthreads();
        if (tid == 0) out[pair] = wsum[0] + wsum[1] + wsum[2] + wsum[3];
        __syncthreads();  // wsum/rowbuf reusable next pair

        pit++;
        if (nxt_pair >= npairs) break;
        pair = nxt_pair;
        gbase = gnxt;
    }
}

// ---------------- launch ----------------
extern "C" void kernel_launch(void* const* d_in, const int* in_sizes, int n_in,
                              void* d_out, int out_size) {
    const float* in = (const float*)d_in[0];
    float* out = (float*)d_out;
    const int pairs = in_sizes[0] / (2 * L * D);  // B*K = 1024

    int sms = 148;
    cudaDeviceGetAttribute(&sms, cudaDevAttrMultiProcessorCount, 0);
    int grid = 2 * sms;
    if (grid > pairs) grid = pairs;

    cudaFuncSetAttribute(som_kernel, cudaFuncAttributeMaxDynamicSharedMemorySize, SMEM_DYN);
    reset_counter<<<1, 1>>>(grid);
    som_kernel<<<grid, NTHR, SMEM_DYN>>>(in, out, pairs);
}

// round 15
// speedup vs baseline: 1.0433x; 1.0171x over previous
#include <cuda_runtime.h>
#include <cstdint>

#define DINL __device__ __forceinline__

// ---------------- problem constants ----------------
static constexpr int L   = 128;  // rows per operand tile (M and N)
static constexpr int D   = 768;  // reduction dim
static constexpr int KC  = 32;   // fp32 elements per K-chunk
static constexpr int NCH = D / KC;  // 24 chunks
static constexpr int STAGES = 3;
static constexpr int NTHR = 128; // 4 warps, 2x2 grid of 64x64 warp tiles

// smem: padded row stride of 36 floats -> conflict-free LDS and STS patterns
static constexpr int RS = 36;                         // row stride in floats
static constexpr int TILE_FLOATS  = L * RS;           // 4608 floats = 18 KB
static constexpr int STAGE_FLOATS = 2 * TILE_FLOATS;  // A + B = 36 KB
static constexpr int HDR_FLOATS   = 288;              // rowbuf[256]+wsum[4]+mbars
static constexpr uint32_t TILE_BYTES  = TILE_FLOATS * 4;   // 18432
static constexpr uint32_t STAGE_BYTES = STAGE_FLOATS * 4;  // 36864
static constexpr uint32_t ROWBLK_BYTES = 16 * RS * 4;      // 2304 (16-row block)
static constexpr uint32_t MBAR_OFF = 264 * 4;              // byte offset of mbarriers
static constexpr uint32_t SMEM_DYN =
    (HDR_FLOATS + STAGES * STAGE_FLOATS) * sizeof(float);  // 111,744 B

// ---------------- PTX helpers ----------------
DINL uint32_t smem_u32(const void* p) {
    uint32_t a;
    asm("{ .reg .u64 t; cvta.to.shared.u64 t, %1; cvt.u32.u64 %0, t; }" : "=r"(a) : "l"(p));
    return a;
}
DINL void cp_async16(uint32_t dst, const void* src) {
    asm volatile("cp.async.cg.shared.global [%0], [%1], 16;" :: "r"(dst), "l"(src) : "memory");
}
DINL void mbar_init(uint32_t a, uint32_t cnt) {
    asm volatile("mbarrier.init.shared.b64 [%0], %1;" :: "r"(a), "r"(cnt) : "memory");
}
DINL void mbar_arrive(uint32_t a) {
    asm volatile("mbarrier.arrive.shared.b64 _, [%0];" :: "r"(a) : "memory");
}
// arrive on mbar when all of this thread's prior cp.async have completed
DINL void cp_async_mbar_arrive(uint32_t a) {
    asm volatile("cp.async.mbarrier.arrive.noinc.shared.b64 [%0];" :: "r"(a) : "memory");
}
DINL void mbar_wait(uint32_t a, uint32_t parity) {
    asm volatile(
        "{\n\t.reg .pred P;\n"
        "WL%=:\n\t"
        "mbarrier.try_wait.parity.shared.b64 P, [%0], %1;\n\t"
        "@P bra WD%=;\n\t"
        "bra WL%=;\n"
        "WD%=:\n\t}"
        :: "r"(a), "r"(parity) : "memory");
}

DINL void mma_tf32(float* d, const uint32_t* a, const uint32_t* b) {
    asm volatile(
        "mma.sync.aligned.m16n8k8.row.col.f32.tf32.tf32.f32 "
        "{%0,%1,%2,%3}, {%4,%5,%6,%7}, {%8,%9}, {%0,%1,%2,%3};\n"
        : "+f"(d[0]), "+f"(d[1]), "+f"(d[2]), "+f"(d[3])
        : "r"(a[0]), "r"(a[1]), "r"(a[2]), "r"(a[3]), "r"(b[0]), "r"(b[1]));
}

DINL uint32_t f2u(float x) { return __float_as_uint(x); }

// A fragments: four 16-row m-tiles at k-offset k0. pA = sA + (wr*64+qid)*RS + qlan.
DINL void load_a(uint32_t (&a)[4][4], const float* __restrict__ pA, int k0) {
#pragma unroll
    for (int mt = 0; mt < 4; mt++) {
        const int base = mt * 16 * RS;
        a[mt][0] = f2u(pA[base + k0]);
        a[mt][1] = f2u(pA[base + 8 * RS + k0]);
        a[mt][2] = f2u(pA[base + k0 + 4]);
        a[mt][3] = f2u(pA[base + 8 * RS + k0 + 4]);
    }
}
// B fragments: eight 8-col n-tiles at k-offset k0. pB = sB + (wc*64+qid)*RS + qlan.
DINL void load_b(uint32_t (&b)[8][2], const float* __restrict__ pB, int k0) {
#pragma unroll
    for (int nt = 0; nt < 8; nt++) {
        b[nt][0] = f2u(pB[nt * 8 * RS + k0]);
        b[nt][1] = f2u(pB[nt * 8 * RS + k0 + 4]);
    }
}

// ---------------- kernel ----------------
// One CTA (128 threads) per (b,k) pair. sim = ctx @ ent^T via tf32 mma.sync;
// out[pair] = sum over rows of rowwise max of sim.
// 2x2 warp grid of 64x64 tiles -> fragment smem traffic (2+2)x16KB per chunk.
// 3-stage cp.async/mbarrier pipeline, no __syncthreads in mainloop, fragment
// register double-buffering, mid-compute refill. (R7 — measured optimum.)
__global__ void __launch_bounds__(NTHR, 2)
som_kernel(const float* __restrict__ in, float* __restrict__ out) {
    extern __shared__ float smem[];
    float* rowbuf = smem;            // [2][128] rowwise maxima (per col-half)
    float* wsum   = smem + 256;      // [4]
    float* tiles  = smem + HDR_FLOATS;

    const int tid  = threadIdx.x;
    const int wid  = tid >> 5;
    const int lane = tid & 31;
    const int wr   = wid >> 1;  // warp row  (rows wr*64 .. +63)
    const int wc   = wid & 1;   // warp col  (cols wc*64 .. +63)
    const int qid  = lane >> 2; // 0..7
    const int qlan = lane & 3;  // 0..3

    const uint32_t smem_b = smem_u32(smem);
    const uint32_t mb_full = smem_b + MBAR_OFF;       // full[0..2]
    const uint32_t mb_free = smem_b + MBAR_OFF + 24;  // free[0..2]

    if (tid == 0) {
#pragma unroll
        for (int s = 0; s < STAGES; s++) {
            mbar_init(mb_full + 8u * s, NTHR);
            mbar_init(mb_free + 8u * s, NTHR);
        }
    }
    __syncthreads();

    const size_t pair = blockIdx.x;
    const float* ctx = in + pair * (size_t)(2 * L * D);

    // ---- cp.async plan: 16x 16B per thread per chunk (8 A-rows + 8 B-rows) ----
    const int lrow = tid >> 3;  // 0..15
    const int lseg = tid & 7;   // 0..7
    const float* gbase = ctx + (size_t)lrow * D + lseg * 4;
    const uint32_t dst0 = smem_u32(tiles) + (uint32_t)(lrow * RS + lseg * 4) * 4u;

    // frag LDS base indices
    const int idxA = (wr * 64 + qid) * RS + qlan;
    const int idxB = (wc * 64 + qid) * RS + qlan;

    // ---- accumulators: 4 m-tiles x 8 n-tiles x 4 regs ----
    float acc[4][8][4];
#pragma unroll
    for (int mt = 0; mt < 4; mt++)
#pragma unroll
        for (int nt = 0; nt < 8; nt++)
#pragma unroll
            for (int r = 0; r < 4; r++) acc[mt][nt][r] = 0.0f;

    // issue cp.async for chunk c into stage c%3, then arm full[s]
    auto issue = [&](int c) {
        const float* pa = gbase + c * KC;
        const uint32_t da = dst0 + (uint32_t)(c % STAGES) * STAGE_BYTES;
#pragma unroll
        for (int i = 0; i < 8; i++) {
            cp_async16(da + i * ROWBLK_BYTES, pa + (size_t)i * 16 * D);
            cp_async16(da + TILE_BYTES + i * ROWBLK_BYTES,
                       pa + (size_t)L * D + (size_t)i * 16 * D);
        }
        cp_async_mbar_arrive(mb_full + 8u * (uint32_t)(c % STAGES));
    };

    // prologue: chunks 0 and 1 in flight
    issue(0);
    issue(1);

    uint32_t A[2][4][4];
    uint32_t Bf[2][8][2];

#pragma unroll 1
    for (int c = 0; c < NCH; c++) {
        const uint32_t s = (uint32_t)(c % STAGES);
        mbar_wait(mb_full + 8u * s, (uint32_t)((c / 3) & 1));  // chunk c visible

        const float* sA = tiles + (size_t)s * STAGE_FLOATS;
        const float* pA = sA + idxA;
        const float* pB = sA + TILE_FLOATS + idxB;

        load_a(A[0], pA, 0);
        load_b(Bf[0], pB, 0);
        // prefetch ks=1 fragments
        load_a(A[1], pA, 8);
        load_b(Bf[1], pB, 8);

        // ks = 0 MMAs
#pragma unroll
        for (int mt = 0; mt < 4; mt++)
#pragma unroll
            for (int nt = 0; nt < 8; nt++)
                mma_tf32(acc[mt][nt], A[0][mt], Bf[0][nt]);

        // mid-compute pipeline refill: stage (c+2)%3 was last read at chunk c-1
        if (c + 2 < NCH) {
            if (c >= 1)
                mbar_wait(mb_free + 8u * (uint32_t)((c + 2) % STAGES),
                          (uint32_t)(((c - 1) / 3) & 1));
            issue(c + 2);
        }

        // ks = 1..3
#pragma unroll
        for (int ks = 1; ks < 4; ks++) {
            const int cur = ks & 1, nxt = cur ^ 1;
            if (ks < 3) {
                load_a(A[nxt], pA, (ks + 1) * 8);
                load_b(Bf[nxt], pB, (ks + 1) * 8);
            }
#pragma unroll
            for (int mt = 0; mt < 4; mt++)
#pragma unroll
                for (int nt = 0; nt < 8; nt++)
                    mma_tf32(acc[mt][nt], A[cur][mt], Bf[cur][nt]);
        }

        // done reading stage s (release orders the LDS reads above)
        mbar_arrive(mb_free + 8u * s);
    }

    // ---- epilogue: rowwise max over this warp's 64 cols, then combine ----
    // acc reg r holds (row = wr*64 + mt*16 + 8*(r>>1) + qid, col = 2*qlan + (r&1) + nt*8)
#pragma unroll
    for (int mt = 0; mt < 4; mt++) {
#pragma unroll
        for (int h = 0; h < 2; h++) {
            float m = __int_as_float(0xff800000);
#pragma unroll
            for (int nt = 0; nt < 8; nt++) {
                m = fmaxf(m, acc[mt][nt][2 * h]);
                m = fmaxf(m, acc[mt][nt][2 * h + 1]);
            }
            m = fmaxf(m, __shfl_xor_sync(0xffffffffu, m, 1));
            m = fmaxf(m, __shfl_xor_sync(0xffffffffu, m, 2));
            if (qlan == 0)
                rowbuf[wc * 128 + wr * 64 + mt * 16 + h * 8 + qid] = m;
        }
    }
    __syncthreads();

    {
        float v = fmaxf(rowbuf[tid], rowbuf[128 + tid]);
#pragma unroll
        for (int o = 16; o > 0; o >>= 1) v += __shfl_xor_sync(0xffffffffu, v, o);
        if (lane == 0) wsum[wid] = v;
    }
    __syncthreads();
    if (tid == 0) out[pair] = wsum[0] + wsum[1] + wsum[2] + wsum[3];
}

// ---------------- launch ----------------
extern "C" void kernel_launch(void* const* d_in, const int* in_sizes, int n_in,
                              void* d_out, int out_size) {
    const float* in = (const float*)d_in[0];
    float* out = (float*)d_out;
    const int pairs = in_sizes[0] / (2 * L * D);  // B*K = 1024

    cudaFuncSetAttribute(som_kernel, cudaFuncAttributeMaxDynamicSharedMemorySize, SMEM_DYN);
    som_kernel<<<pairs, NTHR, SMEM_DYN>>>(in, out);
}

// round 16
// speedup vs baseline: 1.0589x; 1.0149x over previous
#include <cuda_runtime.h>
#include <cstdint>

#define DINL __device__ __forceinline__

// ---------------- problem constants ----------------
static constexpr int L   = 128;  // rows per operand tile (M and N)
static constexpr int D   = 768;  // reduction dim
static constexpr int KC  = 32;   // fp32 elements per K-chunk
static constexpr int NCH = D / KC;  // 24 chunks
static constexpr int STAGES = 3;
static constexpr int NTHR = 160; // warps 0-3 consume (2x2 of 64x64), warp 4 produces
static constexpr int NCONS = 128;

// smem: padded row stride of 36 floats -> conflict-free LDS and STS patterns
static constexpr int RS = 36;                         // row stride in floats
static constexpr int TILE_FLOATS  = L * RS;           // 4608 floats = 18 KB
static constexpr int STAGE_FLOATS = 2 * TILE_FLOATS;  // A + B = 36 KB
static constexpr int HDR_FLOATS   = 288;              // rowbuf[256]+wsum[4]+mbars
static constexpr uint32_t TILE_BYTES  = TILE_FLOATS * 4;   // 18432
static constexpr uint32_t STAGE_BYTES = STAGE_FLOATS * 4;  // 36864
static constexpr uint32_t MBAR_OFF = 264 * 4;              // byte offset of mbarriers
static constexpr uint32_t SMEM_DYN =
    (HDR_FLOATS + STAGES * STAGE_FLOATS) * sizeof(float);  // 111,744 B

// ---------------- PTX helpers ----------------
DINL uint32_t smem_u32(const void* p) {
    uint32_t a;
    asm("{ .reg .u64 t; cvta.to.shared.u64 t, %1; cvt.u32.u64 %0, t; }" : "=r"(a) : "l"(p));
    return a;
}
DINL void cp_async16(uint32_t dst, const void* src) {
    asm volatile("cp.async.cg.shared.global [%0], [%1], 16;" :: "r"(dst), "l"(src) : "memory");
}
DINL void mbar_init(uint32_t a, uint32_t cnt) {
    asm volatile("mbarrier.init.shared.b64 [%0], %1;" :: "r"(a), "r"(cnt) : "memory");
}
DINL void mbar_arrive(uint32_t a) {
    asm volatile("mbarrier.arrive.shared.b64 _, [%0];" :: "r"(a) : "memory");
}
// arrive on mbar when all of this thread's prior cp.async have completed
DINL void cp_async_mbar_arrive(uint32_t a) {
    asm volatile("cp.async.mbarrier.arrive.noinc.shared.b64 [%0];" :: "r"(a) : "memory");
}
DINL void mbar_wait(uint32_t a, uint32_t parity) {
    asm volatile(
        "{\n\t.reg .pred P;\n"
        "WL%=:\n\t"
        "mbarrier.try_wait.parity.shared.b64 P, [%0], %1;\n\t"
        "@P bra WD%=;\n\t"
        "bra WL%=;\n"
        "WD%=:\n\t}"
        :: "r"(a), "r"(parity) : "memory");
}

DINL void mma_tf32(float* d, const uint32_t* a, const uint32_t* b) {
    asm volatile(
        "mma.sync.aligned.m16n8k8.row.col.f32.tf32.tf32.f32 "
        "{%0,%1,%2,%3}, {%4,%5,%6,%7}, {%8,%9}, {%0,%1,%2,%3};\n"
        : "+f"(d[0]), "+f"(d[1]), "+f"(d[2]), "+f"(d[3])
        : "r"(a[0]), "r"(a[1]), "r"(a[2]), "r"(a[3]), "r"(b[0]), "r"(b[1]));
}

DINL uint32_t f2u(float x) { return __float_as_uint(x); }

// A fragments: four 16-row m-tiles at k-offset k0. pA = sA + (wr*64+qid)*RS + qlan.
DINL void load_a(uint32_t (&a)[4][4], const float* __restrict__ pA, int k0) {
#pragma unroll
    for (int mt = 0; mt < 4; mt++) {
        const int base = mt * 16 * RS;
        a[mt][0] = f2u(pA[base + k0]);
        a[mt][1] = f2u(pA[base + 8 * RS + k0]);
        a[mt][2] = f2u(pA[base + k0 + 4]);
        a[mt][3] = f2u(pA[base + 8 * RS + k0 + 4]);
    }
}
// B fragments: eight 8-col n-tiles at k-offset k0. pB = sB + (wc*64+qid)*RS + qlan.
DINL void load_b(uint32_t (&b)[8][2], const float* __restrict__ pB, int k0) {
#pragma unroll
    for (int nt = 0; nt < 8; nt++) {
        b[nt][0] = f2u(pB[nt * 8 * RS + k0]);
        b[nt][1] = f2u(pB[nt * 8 * RS + k0 + 4]);
    }
}

// ---------------- kernel ----------------
// One CTA (160 threads) per (b,k) pair. sim = ctx @ ent^T via tf32 mma.sync;
// out[pair] = sum over rows of rowwise max of sim.
// Warp-specialized: warp 4 is the sole producer (all cp.async + free-waits,
// keeps all 3 stages in flight); warps 0-3 are pure consumers running the R7
// chunk body with no LDGSTS burst and no free-wait in their stream.
__global__ void __launch_bounds__(NTHR, 2)
som_kernel(const float* __restrict__ in, float* __restrict__ out) {
    extern __shared__ float smem[];
    float* rowbuf = smem;            // [2][128] rowwise maxima (per col-half)
    float* wsum   = smem + 256;      // [4]
    float* tiles  = smem + HDR_FLOATS;

    const int tid  = threadIdx.x;
    const int wid  = tid >> 5;
    const int lane = tid & 31;

    const uint32_t smem_b = smem_u32(smem);
    const uint32_t mb_full = smem_b + MBAR_OFF;       // full[0..2]
    const uint32_t mb_free = smem_b + MBAR_OFF + 24;  // free[0..2]

    if (tid == 0) {
#pragma unroll
        for (int s = 0; s < STAGES; s++) {
            mbar_init(mb_full + 8u * s, 32);     // producer lanes arm
            mbar_init(mb_free + 8u * s, NCONS);  // consumers release
        }
    }
    __syncthreads();

    const size_t pair = blockIdx.x;
    const float* ctx = in + pair * (size_t)(2 * L * D);
    const uint32_t tiles_u = smem_u32(tiles);

    if (wid == 4) {
        // ================== PRODUCER WARP ==================
        // lane -> (row4 = lane>>3 in 0..3, seg = lane&7); covers rows row4+4*i.
        const int lrow = lane >> 3;
        const int lseg = lane & 7;
        const float* gbase = ctx + (size_t)lrow * D + lseg * 4;
        const uint32_t dst0 = tiles_u + (uint32_t)(lrow * RS + lseg * 4) * 4u;

#pragma unroll 1
        for (int c = 0; c < NCH; c++) {
            const uint32_t s = (uint32_t)(c % STAGES);
            if (c >= STAGES)
                mbar_wait(mb_free + 8u * s, (uint32_t)(((c - 3) / 3) & 1));
            const float* pa = gbase + c * KC;
            const uint32_t da = dst0 + s * STAGE_BYTES;
#pragma unroll
            for (int i = 0; i < 32; i++) {
                cp_async16(da + (uint32_t)(i * 4 * RS) * 4u,
                           pa + (size_t)i * 4 * D);
                cp_async16(da + TILE_BYTES + (uint32_t)(i * 4 * RS) * 4u,
                           pa + (size_t)L * D + (size_t)i * 4 * D);
            }
            cp_async_mbar_arrive(mb_full + 8u * s);
        }
    } else {
        // ================== CONSUMER WARPS (R7 body) ==================
        const int wr   = wid >> 1;  // warp row  (rows wr*64 .. +63)
        const int wc   = wid & 1;   // warp col  (cols wc*64 .. +63)
        const int qid  = lane >> 2; // 0..7
        const int qlan = lane & 3;  // 0..3

        const int idxA = (wr * 64 + qid) * RS + qlan;
        const int idxB = (wc * 64 + qid) * RS + qlan;

        float acc[4][8][4];
#pragma unroll
        for (int mt = 0; mt < 4; mt++)
#pragma unroll
            for (int nt = 0; nt < 8; nt++)
#pragma unroll
                for (int r = 0; r < 4; r++) acc[mt][nt][r] = 0.0f;

        uint32_t A[2][4][4];
        uint32_t Bf[2][8][2];

#pragma unroll 1
        for (int c = 0; c < NCH; c++) {
            const uint32_t s = (uint32_t)(c % STAGES);
            mbar_wait(mb_full + 8u * s, (uint32_t)((c / 3) & 1));  // chunk visible

            const float* sA = tiles + (size_t)s * STAGE_FLOATS;
            const float* pA = sA + idxA;
            const float* pB = sA + TILE_FLOATS + idxB;

            load_a(A[0], pA, 0);
            load_b(Bf[0], pB, 0);
            load_a(A[1], pA, 8);
            load_b(Bf[1], pB, 8);

            // ks = 0 MMAs
#pragma unroll
            for (int mt = 0; mt < 4; mt++)
#pragma unroll
                for (int nt = 0; nt < 8; nt++)
                    mma_tf32(acc[mt][nt], A[0][mt], Bf[0][nt]);

            // ks = 1..3
#pragma unroll
            for (int ks = 1; ks < 4; ks++) {
                const int cur = ks & 1, nxt = cur ^ 1;
                if (ks < 3) {
                    load_a(A[nxt], pA, (ks + 1) * 8);
                    load_b(Bf[nxt], pB, (ks + 1) * 8);
                }
#pragma unroll
                for (int mt = 0; mt < 4; mt++)
#pragma unroll
                    for (int nt = 0; nt < 8; nt++)
                        mma_tf32(acc[mt][nt], A[cur][mt], Bf[cur][nt]);
            }

            mbar_arrive(mb_free + 8u * s);  // done reading stage s
        }

        // ---- epilogue: rowwise max over this warp's 64 cols ----
#pragma unroll
        for (int mt = 0; mt < 4; mt++) {
#pragma unroll
            for (int h = 0; h < 2; h++) {
                float m = __int_as_float(0xff800000);
#pragma unroll
                for (int nt = 0; nt < 8; nt++) {
                    m = fmaxf(m, acc[mt][nt][2 * h]);
                    m = fmaxf(m, acc[mt][nt][2 * h + 1]);
                }
                m = fmaxf(m, __shfl_xor_sync(0xffffffffu, m, 1));
                m = fmaxf(m, __shfl_xor_sync(0xffffffffu, m, 2));
                if (qlan == 0)
                    rowbuf[wc * 128 + wr * 64 + mt * 16 + h * 8 + qid] = m;
            }
        }
    }

    __syncthreads();

    if (tid < NCONS) {
        float v = fmaxf(rowbuf[tid], rowbuf[128 + tid]);
#pragma unroll
        for (int o = 16; o > 0; o >>= 1) v += __shfl_xor_sync(0xffffffffu, v, o);
        if (lane == 0) wsum[wid] = v;
    }
    __syncthreads();
    if (tid == 0) out[pair] = wsum[0] + wsum[1] + wsum[2] + wsum[3];
}

// ---------------- launch ----------------
extern "C" void kernel_launch(void* const* d_in, const int* in_sizes, int n_in,
                              void* d_out, int out_size) {
    const float* in = (const float*)d_in[0];
    float* out = (float*)d_out;
    const int pairs = in_sizes[0] / (2 * L * D);  // B*K = 1024

    cudaFuncSetAttribute(som_kernel, cudaFuncAttributeMaxDynamicSharedMemorySize, SMEM_DYN);
    som_kernel<<<pairs, NTHR, SMEM_DYN>>>(in, out);
}